// round 15
// baseline (speedup 1.0000x reference)
#include <cuda_runtime.h>
#include <cuda_fp16.h>
#include <cstdint>
#include <cmath>

// Problem constants
#define NB 64          // batch
#define NS 16          // steps
#define NO 31          // opcodes
#define ND 1024        // hidden dim
#define KTOT (NO*ND)   // 31744
#define BK 32          // one K-slab
#define NPAIR 16       // 32 slabs = 16 pairs per step
#define BN 128
#define NTILES (ND/BN) // 8
#define NSLAB 6        // slab buffers in ring
#define NCTA (NTILES*NO)   // 248

// smem slab geometry (halves)
#define A_STRIDE 40
#define B_STRIDE 136
#define A_SLAB (64 * A_STRIDE)     // 2560 halves = 5120 B
#define B_SLAB (32 * B_STRIDE)     // 4352 halves = 8704 B
#define SMEM_BYTES (NSLAB * (A_SLAB + B_SLAB) * 2)   // 82944 B

// ---------------- device scratch ----------------
__device__ __half  g_Kh[(size_t)KTOT * ND];        // 65 MB fp16 kernels [o*1024+d][n]
__device__ __half  g_hh[NB * ND];                  // fp16 hidden (GEMM A operand)
__device__ float   g_h[NB * ND];                   // fp32 hidden state
__device__ float   g_partial[NO * NB * ND];        // per-opcode partials (w applied)
__device__ float   g_w[NS][NB][NO];                // softmax weights
__device__ float   g_gate[NS][NB];                 // sigmoid gates
// hierarchical barrier state (monotone counters: replay-safe)
__device__ volatile unsigned g_gen;
__device__ unsigned g_cnt_sub[NTILES][64];
__device__ unsigned g_cnt_top;

// ---------------- helpers ----------------
__device__ __forceinline__ uint32_t smem_u32(const void* p) {
    return (uint32_t)__cvta_generic_to_shared(p);
}
__device__ __forceinline__ void cp_async16(uint32_t dst, const void* src) {
    asm volatile("cp.async.cg.shared.global [%0], [%1], 16;\n" :: "r"(dst), "l"(src));
}
__device__ __forceinline__ void cp_commit() {
    asm volatile("cp.async.commit_group;\n");
}
__device__ __forceinline__ void cp_wait1() {
    asm volatile("cp.async.wait_group 1;\n");
}
__device__ __forceinline__ void ldm_x4(uint32_t* r, uint32_t addr) {
    asm volatile("ldmatrix.sync.aligned.m8n8.x4.shared.b16 {%0,%1,%2,%3}, [%4];\n"
                 : "=r"(r[0]), "=r"(r[1]), "=r"(r[2]), "=r"(r[3]) : "r"(addr));
}
__device__ __forceinline__ void ldm_x4t(uint32_t* r, uint32_t addr) {
    asm volatile("ldmatrix.sync.aligned.m8n8.x4.trans.shared.b16 {%0,%1,%2,%3}, [%4];\n"
                 : "=r"(r[0]), "=r"(r[1]), "=r"(r[2]), "=r"(r[3]) : "r"(addr));
}
__device__ __forceinline__ void mma16816(float* c, const uint32_t* a, uint32_t b0, uint32_t b1) {
    asm volatile(
        "mma.sync.aligned.m16n8k16.row.col.f32.f16.f16.f32 "
        "{%0,%1,%2,%3}, {%4,%5,%6,%7}, {%8,%9}, {%0,%1,%2,%3};\n"
        : "+f"(c[0]), "+f"(c[1]), "+f"(c[2]), "+f"(c[3])
        : "r"(a[0]), "r"(a[1]), "r"(a[2]), "r"(a[3]), "r"(b0), "r"(b1));
}

// Hierarchical replay-safe grid barrier.
__device__ __forceinline__ void grid_barrier(int sub, unsigned target) {
    __syncthreads();
    if (threadIdx.x == 0) {
        __threadfence();
        unsigned r = atomicAdd(&g_cnt_sub[sub][0], 1u) + 1u;
        if (r % NO == 0u) {
            unsigned r2 = atomicAdd(&g_cnt_top, 1u) + 1u;
            if (r2 % NTILES == 0u) atomicAdd((unsigned*)&g_gen, 1u);
        }
        while ((int)(g_gen - target) < 0) __nanosleep(32);
        __threadfence();
    }
    __syncthreads();
}

// ---------------- single fused persistent kernel ----------------
// grid 248 = (31 opcodes) x (8 N-tiles), 256 threads.
// 8 warps = 2 K-groups x (2x2 warp grid, 32x64 warp tiles) over the 64x128 CTA tile.
// Group g consumes slabs {2p+g}; accumulators merged once per step via smem.
__global__ __launch_bounds__(256, 2) void npi_persistent(
    const float* __restrict__ logits, const float* __restrict__ operands,
    const float* __restrict__ signal, const float* __restrict__ opk,
    float* __restrict__ out) {
    const int bid = blockIdx.x;
    const int ks = bid >> 3;        // opcode  0..30
    const int ntile = bid & 7;      // N tile  0..7
    const int tid = threadIdx.x;
    const int wid = tid >> 5, lane = tid & 31;
    const int grp = wid >> 2;       // K-group 0/1
    const int lwid = wid & 3;       // warp within group
    const int wm = lwid & 1, wn = lwid >> 1;   // 2x2 grid; tile 32(m) x 64(n)

    extern __shared__ __half smem_dyn[];
    __half* As = smem_dyn;                     // [NSLAB][A_SLAB]
    __half* Bs = smem_dyn + NSLAB * A_SLAB;    // [NSLAB][B_SLAB]
    __shared__ unsigned s_gen0;
    __shared__ float s_w[NB];

    if (tid == 0) s_gen0 = g_gen;
    __syncthreads();
    unsigned nbar = 0;

    // ---- phase 0a: convert op_kernels fp32 -> fp16 (grid-strided) ----
    {
        const size_t total8 = (size_t)KTOT * ND / 8;
        for (size_t c8 = (size_t)bid * 256 + tid; c8 < total8; c8 += (size_t)NCTA * 256) {
            size_t i = c8 * 8;
            float4 f0 = *(const float4*)(opk + i);
            float4 f1 = *(const float4*)(opk + i + 4);
            __half2* dst = (__half2*)(g_Kh + i);
            dst[0] = __floats2half2_rn(f0.x, f0.y);
            dst[1] = __floats2half2_rn(f0.z, f0.w);
            dst[2] = __floats2half2_rn(f1.x, f1.y);
            dst[3] = __floats2half2_rn(f1.z, f1.w);
        }
    }

    // ---- phase 0b: softmax weights + gates (one warp per (b,s)) ----
    {
        int gw = bid * 8 + wid;
        if (gw < NB * NS) {
            int b = gw >> 4, s = gw & 15;
            float v = (lane < NO) ? logits[gw * NO + lane] : -INFINITY;
            float m = v;
            #pragma unroll
            for (int off = 16; off > 0; off >>= 1)
                m = fmaxf(m, __shfl_xor_sync(0xffffffffu, m, off));
            float e = (lane < NO) ? expf(v - m) : 0.0f;
            float sum = e;
            #pragma unroll
            for (int off = 16; off > 0; off >>= 1)
                sum += __shfl_xor_sync(0xffffffffu, sum, off);
            if (lane < NO) g_w[s][b][lane] = e / sum;
            if (lane == 0) g_gate[s][b] = 1.0f / (1.0f + expf(-operands[gw * 4 + 3]));
        }
    }

    // ---- phase 0c: init h = signal (fp32 + fp16 copies) ----
    const int gidx = bid * 256 + tid;        // 32768 float2 items
    if (gidx < NB * ND / 2) {
        float2 s = ((const float2*)signal)[gidx];
        ((float2*)g_h)[gidx] = s;
        ((__half2*)g_hh)[gidx] = __floats2half2_rn(s.x, s.y);
    }
    grid_barrier(ntile, s_gen0 + ++nbar);

    const int k0 = ks * ND;                      // row base into g_Kh
    const int nbase = ntile * BN;
    const int arow = tid >> 2, ach = tid & 3;    // A slab: 64 rows x 4 chunks (1/thread)
    const int brow = tid >> 4, bch = tid & 15;   // B slab: 16 rows x 16 chunks (2/thread)
    float* pp = g_partial + (size_t)ks * NB * ND;

    // load one slab pair (slabs 2p, 2p+1) into ring buffers (2p)%6, (2p+1)%6
    #define LOAD_PAIR(p) do {                                                          \
        _Pragma("unroll")                                                              \
        for (int ss = 0; ss < 2; ++ss) {                                               \
            const int slab = 2 * (p) + ss;                                             \
            const int sb = slab % NSLAB;                                               \
            const int d0 = slab * BK;                                                  \
            cp_async16(smem_u32(&As[sb * A_SLAB + arow * A_STRIDE + ach * 8]),         \
                       g_hh + arow * ND + d0 + ach * 8);                               \
            cp_async16(smem_u32(&Bs[sb * B_SLAB + brow * B_STRIDE + bch * 8]),         \
                       g_Kh + (size_t)(k0 + d0 + brow) * ND + nbase + bch * 8);        \
            cp_async16(smem_u32(&Bs[sb * B_SLAB + (brow + 16) * B_STRIDE + bch * 8]),  \
                       g_Kh + (size_t)(k0 + d0 + brow + 16) * ND + nbase + bch * 8);   \
        }                                                                              \
    } while (0)

    for (int t = 0; t < NS; ++t) {
        if (tid < NB) s_w[tid] = g_w[t][tid][ks];

        float c[2][8][4];
        #pragma unroll
        for (int i = 0; i < 2; i++)
            #pragma unroll
            for (int j = 0; j < 8; j++)
                #pragma unroll
                for (int q = 0; q < 4; q++) c[i][j][q] = 0.0f;

        LOAD_PAIR(0);
        cp_commit();
        LOAD_PAIR(1);
        cp_commit();

        for (int p = 0; p < NPAIR; ++p) {
            const int sb = (2 * p + grp) % NSLAB;    // this group's slab buffer
            cp_wait1();
            __syncthreads();          // pair p visible; pair p-1 readers done

            if (p + 2 < NPAIR) {
                LOAD_PAIR(p + 2);
            }
            cp_commit();              // always commit (uniform group count)

            #pragma unroll
            for (int kh = 0; kh < 2; ++kh) {
                uint32_t a[2][4];
                #pragma unroll
                for (int mf = 0; mf < 2; ++mf) {
                    uint32_t addr = smem_u32(
                        &As[sb * A_SLAB + (wm * 32 + mf * 16 + (lane & 15)) * A_STRIDE
                            + kh * 16 + (lane >> 4) * 8]);
                    ldm_x4(a[mf], addr);
                }
                uint32_t bb[4][4];
                #pragma unroll
                for (int np = 0; np < 4; ++np) {
                    uint32_t addr = smem_u32(
                        &Bs[sb * B_SLAB + (kh * 16 + (lane & 15)) * B_STRIDE
                            + wn * 64 + np * 16 + (lane >> 4) * 8]);
                    ldm_x4t(bb[np], addr);
                }
                #pragma unroll
                for (int mf = 0; mf < 2; ++mf)
                    #pragma unroll
                    for (int nf = 0; nf < 8; ++nf)
                        mma16816(c[mf][nf], a[mf], bb[nf >> 1][(nf & 1) * 2], bb[nf >> 1][(nf & 1) * 2 + 1]);
            }
        }
        __syncthreads();   // all slab reads done; buffers reusable as exchange

        // ---- merge the two K-groups' accumulators via smem, then store partial ----
        float* exch = (float*)smem_dyn;          // 64x128 f32 = 32 KB (fits in ring)
        const int m0 = wm * 32 + (lane >> 2);
        const int nb0 = wn * 64 + (lane & 3) * 2;
        if (grp == 1) {
            #pragma unroll
            for (int mf = 0; mf < 2; ++mf)
                #pragma unroll
                for (int nf = 0; nf < 8; ++nf) {
                    int m = m0 + mf * 16;
                    int n = nb0 + nf * 8;
                    exch[m * 128 + n]           = c[mf][nf][0];
                    exch[m * 128 + n + 1]       = c[mf][nf][1];
                    exch[(m + 8) * 128 + n]     = c[mf][nf][2];
                    exch[(m + 8) * 128 + n + 1] = c[mf][nf][3];
                }
        }
        __syncthreads();
        if (grp == 0) {
            #pragma unroll
            for (int mf = 0; mf < 2; ++mf) {
                const int m = m0 + mf * 16;
                const float wA = s_w[m];
                const float wB = s_w[m + 8];
                #pragma unroll
                for (int nf = 0; nf < 8; ++nf) {
                    int n = nb0 + nf * 8;
                    pp[(size_t)m * ND + nbase + n] =
                        wA * (c[mf][nf][0] + exch[m * 128 + n]);
                    pp[(size_t)m * ND + nbase + n + 1] =
                        wA * (c[mf][nf][1] + exch[m * 128 + n + 1]);
                    pp[(size_t)(m + 8) * ND + nbase + n] =
                        wB * (c[mf][nf][2] + exch[(m + 8) * 128 + n]);
                    pp[(size_t)(m + 8) * ND + nbase + n + 1] =
                        wB * (c[mf][nf][3] + exch[(m + 8) * 128 + n + 1]);
                }
            }
        }
        grid_barrier(ntile, s_gen0 + ++nbar);

        // ---- update phase: reduce 31 partials, gate, refresh h ----
        if (gidx < NB * ND / 2) {
            const int b = gidx >> 9;
            float2 tr = make_float2(0.0f, 0.0f);
            #pragma unroll
            for (int o = 0; o < NO; ++o) {
                float2 p = ((const float2*)(g_partial + (size_t)o * NB * ND))[gidx];
                tr.x += p.x;
                tr.y += p.y;
            }
            const float g = g_gate[t][b];
            float2 h = ((const float2*)g_h)[gidx];
            float2 hn;
            hn.x = g * tr.x + (1.0f - g) * h.x;
            hn.y = g * tr.y + (1.0f - g) * h.y;
            if (t == NS - 1) {
                ((float2*)out)[gidx] = hn;
            } else {
                ((float2*)g_h)[gidx] = hn;
                ((__half2*)g_hh)[gidx] = __floats2half2_rn(hn.x, hn.y);
            }
        }
        if (t != NS - 1) grid_barrier(ntile, s_gen0 + ++nbar);
    }
}

// ---------------- launch ----------------
extern "C" void kernel_launch(void* const* d_in, const int* in_sizes, int n_in,
                              void* d_out, int out_size) {
    const float* logits   = (const float*)d_in[0];  // (64,16,31)
    const float* operands = (const float*)d_in[1];  // (64,16,4)
    const float* signal   = (const float*)d_in[2];  // (64,1024)
    const float* opk      = (const float*)d_in[3];  // (31,1024,1024)
    float* out = (float*)d_out;                     // (64,1024)

    cudaFuncSetAttribute(npi_persistent,
                         cudaFuncAttributeMaxDynamicSharedMemorySize, SMEM_BYTES);
    npi_persistent<<<NCTA, 256, SMEM_BYTES>>>(logits, operands, signal, opk, out);
}

// round 17
// speedup vs baseline: 1.1474x; 1.1474x over previous
#include <cuda_runtime.h>
#include <cuda_fp16.h>
#include <cstdint>
#include <cmath>

// Problem constants
#define NB 64          // batch
#define NS 16          // steps
#define NO 31          // opcodes
#define ND 1024        // hidden dim
#define KTOT (NO*ND)   // 31744
#define BK 32
#define NIT (ND/BK)    // 32 K-slabs per step
#define BN 128
#define NTILES (ND/BN) // 8
#define STAGES 3
#define NCTA (NTILES*NO)   // 248
#define PSLAB 7            // K-slabs of B kept persistent in smem

// smem geometry (halves)
#define A_STRIDE 40
#define B_STRIDE 136
#define A_SLAB (64 * A_STRIDE)     // 2560
#define B_SLAB (32 * B_STRIDE)     // 4352
#define PB_HALVES (PSLAB * 32 * B_STRIDE)   // 224*136 = 30464
#define SMEM_HALVES (PB_HALVES + STAGES * (A_SLAB + B_SLAB))
#define SMEM_BYTES (SMEM_HALVES * 2)        // 102400 B

// balanced update partition: 32768 float2 items over 248 CTAs
#define UPD_ITEMS (NB*ND/2)            // 32768
#define UPD_BASE 132
#define UPD_REM (UPD_ITEMS - NCTA*UPD_BASE)   // 32

// ---------------- device scratch ----------------
__device__ __half  g_Kh[(size_t)KTOT * ND];        // 65 MB fp16 kernels [o*1024+d][n]
__device__ __half  g_hh[NB * ND];                  // fp16 hidden (GEMM A operand)
__device__ float   g_h[NB * ND];                   // fp32 hidden state
__device__ float   g_partial[(size_t)NO * NB * ND];// fp32 per-opcode partials (w applied)
__device__ float   g_w[NS][NB][NO];                // softmax weights
__device__ float   g_gate[NS][NB];                 // sigmoid gates
// hierarchical barrier state (monotone counters: replay-safe)
__device__ volatile unsigned g_gen;
__device__ unsigned g_cnt_sub[NTILES][64];
__device__ unsigned g_cnt_top;

// ---------------- helpers ----------------
__device__ __forceinline__ uint32_t smem_u32(const void* p) {
    return (uint32_t)__cvta_generic_to_shared(p);
}
__device__ __forceinline__ void cp_async16(uint32_t dst, const void* src) {
    asm volatile("cp.async.cg.shared.global [%0], [%1], 16;\n" :: "r"(dst), "l"(src));
}
__device__ __forceinline__ void cp_commit() {
    asm volatile("cp.async.commit_group;\n");
}
__device__ __forceinline__ void cp_wait1() {
    asm volatile("cp.async.wait_group 1;\n");
}
__device__ __forceinline__ void ldm_x4(uint32_t* r, uint32_t addr) {
    asm volatile("ldmatrix.sync.aligned.m8n8.x4.shared.b16 {%0,%1,%2,%3}, [%4];\n"
                 : "=r"(r[0]), "=r"(r[1]), "=r"(r[2]), "=r"(r[3]) : "r"(addr));
}
__device__ __forceinline__ void ldm_x4t(uint32_t* r, uint32_t addr) {
    asm volatile("ldmatrix.sync.aligned.m8n8.x4.trans.shared.b16 {%0,%1,%2,%3}, [%4];\n"
                 : "=r"(r[0]), "=r"(r[1]), "=r"(r[2]), "=r"(r[3]) : "r"(addr));
}
__device__ __forceinline__ void mma16816(float* c, const uint32_t* a, uint32_t b0, uint32_t b1) {
    asm volatile(
        "mma.sync.aligned.m16n8k16.row.col.f32.f16.f16.f32 "
        "{%0,%1,%2,%3}, {%4,%5,%6,%7}, {%8,%9}, {%0,%1,%2,%3};\n"
        : "+f"(c[0]), "+f"(c[1]), "+f"(c[2]), "+f"(c[3])
        : "r"(a[0]), "r"(a[1]), "r"(a[2]), "r"(a[3]), "r"(b0), "r"(b1));
}

// Hierarchical replay-safe grid barrier.
__device__ __forceinline__ void grid_barrier(int sub, unsigned target) {
    __syncthreads();
    if (threadIdx.x == 0) {
        __threadfence();
        unsigned r = atomicAdd(&g_cnt_sub[sub][0], 1u) + 1u;
        if (r % NO == 0u) {
            unsigned r2 = atomicAdd(&g_cnt_top, 1u) + 1u;
            if (r2 % NTILES == 0u) atomicAdd((unsigned*)&g_gen, 1u);
        }
        while ((int)(g_gen - target) < 0) __nanosleep(32);
        __threadfence();
    }
    __syncthreads();
}

// ---------------- single fused persistent kernel ----------------
// grid 248 = (31 opcodes) x (8 N-tiles), 256 threads, occ 2.
// B slabs 0..6 persist in smem across all 16 steps; slabs 7..31 stream via ring.
__global__ __launch_bounds__(256, 2) void npi_persistent(
    const float* __restrict__ logits, const float* __restrict__ operands,
    const float* __restrict__ signal, const float* __restrict__ opk,
    float* __restrict__ out) {
    const int bid = blockIdx.x;
    const int ks = bid >> 3;        // opcode  0..30
    const int ntile = bid & 7;      // N tile  0..7
    const int tid = threadIdx.x;
    const int wid = tid >> 5, lane = tid & 31;
    const int wm = wid & 1, wn = wid >> 1;

    extern __shared__ __half smem_dyn[];
    __half* PB = smem_dyn;                             // [224][136] persistent B
    __half* As = smem_dyn + PB_HALVES;                 // [STAGES][A_SLAB]
    __half* Bs = smem_dyn + PB_HALVES + STAGES * A_SLAB;   // [STAGES][B_SLAB]
    __shared__ unsigned s_gen0;
    __shared__ float s_w[NB];

    if (tid == 0) s_gen0 = g_gen;
    __syncthreads();
    unsigned nbar = 0;

    // ---- phase 0a: convert op_kernels fp32 -> fp16 (grid-strided) ----
    {
        const size_t total8 = (size_t)KTOT * ND / 8;
        for (size_t c8 = (size_t)bid * 256 + tid; c8 < total8; c8 += (size_t)NCTA * 256) {
            size_t i = c8 * 8;
            float4 f0 = *(const float4*)(opk + i);
            float4 f1 = *(const float4*)(opk + i + 4);
            __half2* dst = (__half2*)(g_Kh + i);
            dst[0] = __floats2half2_rn(f0.x, f0.y);
            dst[1] = __floats2half2_rn(f0.z, f0.w);
            dst[2] = __floats2half2_rn(f1.x, f1.y);
            dst[3] = __floats2half2_rn(f1.z, f1.w);
        }
    }

    // ---- phase 0b: softmax weights + gates (one warp per (b,s)) ----
    {
        int gw = bid * 8 + wid;
        if (gw < NB * NS) {
            int b = gw >> 4, s = gw & 15;
            float v = (lane < NO) ? logits[gw * NO + lane] : -INFINITY;
            float m = v;
            #pragma unroll
            for (int off = 16; off > 0; off >>= 1)
                m = fmaxf(m, __shfl_xor_sync(0xffffffffu, m, off));
            float e = (lane < NO) ? expf(v - m) : 0.0f;
            float sum = e;
            #pragma unroll
            for (int off = 16; off > 0; off >>= 1)
                sum += __shfl_xor_sync(0xffffffffu, sum, off);
            if (lane < NO) g_w[s][b][lane] = e / sum;
            if (lane == 0) g_gate[s][b] = 1.0f / (1.0f + expf(-operands[gw * 4 + 3]));
        }
    }

    // ---- update-ownership: balanced over ALL 248 CTAs, coalesced per CTA ----
    const int upd_cnt = UPD_BASE + (bid < UPD_REM ? 1 : 0);
    const int upd_start = bid * UPD_BASE + (bid < UPD_REM ? bid : UPD_REM);
    const int item = upd_start + tid;                 // float2 index into h
    const bool upd_act = (tid < upd_cnt);

    // ---- phase 0c: init h = signal (fp32 + fp16 copies) ----
    if (upd_act) {
        float2 s = ((const float2*)signal)[item];
        ((float2*)g_h)[item] = s;
        ((__half2*)g_hh)[item] = __floats2half2_rn(s.x, s.y);
    }
    grid_barrier(ntile, s_gen0 + ++nbar);   // g_Kh fully converted after this

    const int k0 = ks * ND;                      // row base into g_Kh
    const int nbase = ntile * BN;
    const int arow = tid >> 2, ach = tid & 3;    // A loader: 64 rows x 4 chunks
    const int brow = tid >> 4, bch = tid & 15;   // B loader: 16 rows x 16 chunks (x2)
    float* pp = g_partial + (size_t)ks * NB * ND;

    // ---- load persistent B slabs 0..6 (once) ----
    for (int j = tid; j < PSLAB * 32 * 16; j += 256) {
        int row = j >> 4, c8 = j & 15;           // row 0..223, chunk 0..15
        cp_async16(smem_u32(&PB[row * B_STRIDE + c8 * 8]),
                   g_Kh + (size_t)(k0 + row) * ND + nbase + c8 * 8);
    }
    cp_commit();

    // A always ringed; B ringed only for slabs >= PSLAB
    #define LOAD_TILES(buf, slab) do {                                                \
        const int d0_ = (slab) * BK;                                                  \
        cp_async16(smem_u32(&As[(buf) * A_SLAB + arow * A_STRIDE + ach * 8]),         \
                   g_hh + arow * ND + d0_ + ach * 8);                                 \
        if ((slab) >= PSLAB) {                                                        \
            cp_async16(smem_u32(&Bs[(buf) * B_SLAB + brow * B_STRIDE + bch * 8]),     \
                       g_Kh + (size_t)(k0 + d0_ + brow) * ND + nbase + bch * 8);      \
            cp_async16(smem_u32(&Bs[(buf) * B_SLAB + (brow + 16) * B_STRIDE + bch * 8]), \
                       g_Kh + (size_t)(k0 + d0_ + brow + 16) * ND + nbase + bch * 8); \
        }                                                                             \
    } while (0)

    for (int t = 0; t < NS; ++t) {
        if (tid < NB) s_w[tid] = g_w[t][tid][ks];

        float c[2][4][4];
        #pragma unroll
        for (int i = 0; i < 2; i++)
            #pragma unroll
            for (int j = 0; j < 4; j++)
                #pragma unroll
                for (int q = 0; q < 4; q++) c[i][j][q] = 0.0f;

        LOAD_TILES(0, 0);
        cp_commit();
        LOAD_TILES(1, 1);
        cp_commit();

        for (int it = 0; it < NIT; ++it) {
            const int buf = it % STAGES;
            cp_wait1();
            __syncthreads();        // publishes stage `it` (and PB on step 0, iter 0)

            if (it + 2 < NIT) {
                LOAD_TILES((it + 2) % STAGES, it + 2);
            }
            cp_commit();

            #pragma unroll
            for (int kh = 0; kh < 2; ++kh) {
                uint32_t a[2][4];
                #pragma unroll
                for (int mf = 0; mf < 2; ++mf) {
                    uint32_t addr = smem_u32(
                        &As[buf * A_SLAB + (wm * 32 + mf * 16 + (lane & 15)) * A_STRIDE
                            + kh * 16 + (lane >> 4) * 8]);
                    ldm_x4(a[mf], addr);
                }
                const __half* Bbase = (it < PSLAB)
                    ? &PB[(it * 32) * B_STRIDE]
                    : &Bs[buf * B_SLAB];
                uint32_t bb[2][4];
                #pragma unroll
                for (int np = 0; np < 2; ++np) {
                    uint32_t addr = smem_u32(
                        Bbase + (kh * 16 + (lane & 15)) * B_STRIDE
                              + wn * 32 + np * 16 + (lane >> 4) * 8);
                    ldm_x4t(bb[np], addr);
                }
                #pragma unroll
                for (int mf = 0; mf < 2; ++mf)
                    #pragma unroll
                    for (int nf = 0; nf < 4; ++nf)
                        mma16816(c[mf][nf], a[mf], bb[nf >> 1][(nf & 1) * 2], bb[nf >> 1][(nf & 1) * 2 + 1]);
            }
        }
        __syncthreads();   // all reads done before next step's preload reuses stages

        // epilogue: scale by w[t][b][ks] (fp32) and store partial
        #pragma unroll
        for (int mf = 0; mf < 2; ++mf) {
            const int m = wm * 32 + mf * 16 + (lane >> 2);
            const float wA = s_w[m];
            const float wB = s_w[m + 8];
            #pragma unroll
            for (int nf = 0; nf < 4; ++nf) {
                int n = nbase + wn * 32 + nf * 8 + (lane & 3) * 2;
                pp[(size_t)m * ND + n]           = wA * c[mf][nf][0];
                pp[(size_t)m * ND + n + 1]       = wA * c[mf][nf][1];
                pp[(size_t)(m + 8) * ND + n]     = wB * c[mf][nf][2];
                pp[(size_t)(m + 8) * ND + n + 1] = wB * c[mf][nf][3];
            }
        }
        grid_barrier(ntile, s_gen0 + ++nbar);

        // ---- update phase: reduce 31 partials, gate, refresh h ----
        if (upd_act) {
            const int b = item >> 9;       // 512 float2 per batch row
            float2 tr = make_float2(0.0f, 0.0f);
            #pragma unroll
            for (int o = 0; o < NO; ++o) {
                float2 p = ((const float2*)(g_partial + (size_t)o * NB * ND))[item];
                tr.x += p.x;
                tr.y += p.y;
            }
            const float g = g_gate[t][b];
            float2 h = ((const float2*)g_h)[item];
            float2 hn;
            hn.x = g * tr.x + (1.0f - g) * h.x;
            hn.y = g * tr.y + (1.0f - g) * h.y;
            if (t == NS - 1) {
                ((float2*)out)[item] = hn;
            } else {
                ((float2*)g_h)[item] = hn;
                ((__half2*)g_hh)[item] = __floats2half2_rn(hn.x, hn.y);
            }
        }
        if (t != NS - 1) grid_barrier(ntile, s_gen0 + ++nbar);
    }
}

// ---------------- launch ----------------
extern "C" void kernel_launch(void* const* d_in, const int* in_sizes, int n_in,
                              void* d_out, int out_size) {
    const float* logits   = (const float*)d_in[0];  // (64,16,31)
    const float* operands = (const float*)d_in[1];  // (64,16,4)
    const float* signal   = (const float*)d_in[2];  // (64,1024)
    const float* opk      = (const float*)d_in[3];  // (31,1024,1024)
    float* out = (float*)d_out;                     // (64,1024)

    cudaFuncSetAttribute(npi_persistent,
                         cudaFuncAttributeMaxDynamicSharedMemorySize, SMEM_BYTES);
    npi_persistent<<<NCTA, 256, SMEM_BYTES>>>(logits, operands, signal, opk, out);
}